// round 2
// baseline (speedup 1.0000x reference)
#include <cuda_runtime.h>
#include <cuda_bf16.h>

// TopKPool_16372415332892
// x: [B*N, D] f32, weight: [D] f32, edge_index/batch: dead inputs.
// out: [B, D] f32 = mean over top-K(score) rows of x*tanh(score), score = (x.w)/||w||.
// B=256, N=512, D=256, K=256.

#define BB 256
#define NN 512
#define DD 256
#define KK 256
#define THREADS 256

__global__ __launch_bounds__(THREADS, 2)
void topkpool_fused_kernel(const float* __restrict__ x,
                           const float* __restrict__ w,
                           float* __restrict__ out)
{
    __shared__ float sh_score[NN];      // raw dot products
    __shared__ float sh_gate[KK];       // tanh-gated scores, compacted by rank
    __shared__ int   sh_idx[KK];        // selected node indices, compacted by rank
    __shared__ float sh_red[8];
    __shared__ float sh_inv_norm;

    const int b    = blockIdx.x;
    const int tid  = threadIdx.x;
    const int lane = tid & 31;
    const int warp = tid >> 5;

    // ---- ||w|| (recomputed per block; trivial) ----
    {
        float v = w[tid];
        float ssq = v * v;
        #pragma unroll
        for (int o = 16; o; o >>= 1) ssq += __shfl_xor_sync(0xffffffffu, ssq, o);
        if (lane == 0) sh_red[warp] = ssq;
    }
    __syncthreads();
    if (tid == 0) {
        float t = 0.f;
        #pragma unroll
        for (int i = 0; i < 8; i++) t += sh_red[i];
        sh_inv_norm = rsqrtf(t);
    }

    // Per-lane weight fragment in registers: cols [lane*4, lane*4+4) and [128+lane*4, ...)
    const float4 wa = *reinterpret_cast<const float4*>(w + lane * 4);
    const float4 wb = *reinterpret_cast<const float4*>(w + 128 + lane * 4);
    __syncthreads();

    const float* xb = x + (size_t)b * NN * DD;

    // ---- Phase 1: dot products, one warp per row, 64 rows/warp ----
    for (int r = warp; r < NN; r += 8) {
        const float* row = xb + (size_t)r * DD;
        const float4 xa = *reinterpret_cast<const float4*>(row + lane * 4);
        const float4 xc = *reinterpret_cast<const float4*>(row + 128 + lane * 4);
        float d = xa.x * wa.x + xa.y * wa.y + xa.z * wa.z + xa.w * wa.w
                + xc.x * wb.x + xc.y * wb.y + xc.z * wb.z + xc.w * wb.w;
        #pragma unroll
        for (int o = 16; o; o >>= 1) d += __shfl_xor_sync(0xffffffffu, d, o);
        if (lane == 0) sh_score[r] = d;
    }
    __syncthreads();

    // ---- Phase 2: exact rank via count-of-greater (tie-break: smaller index wins,
    // matching jax.lax.top_k). Rank is unique per node -> free compaction. ----
    const float inv_norm = sh_inv_norm;
    #pragma unroll
    for (int h = 0; h < 2; h++) {
        const int i = tid + h * THREADS;
        const float si = sh_score[i];
        int cnt = 0;
        #pragma unroll 8
        for (int j = 0; j < NN; j++) {
            const float sj = sh_score[j];
            cnt += (sj > si) || (sj == si && j < i);
        }
        if (cnt < KK) {
            sh_idx[cnt]  = i;
            sh_gate[cnt] = tanhf(si * inv_norm);
        }
    }
    __syncthreads();

    // ---- Phase 3: out[b][tid] = (1/K) * sum_k x[idx[k]][tid] * gate[k] ----
    float acc = 0.f;
    #pragma unroll 8
    for (int k = 0; k < KK; k++) {
        acc += xb[(size_t)sh_idx[k] * DD + tid] * sh_gate[k];
    }
    out[(size_t)b * DD + tid] = acc * (1.0f / (float)KK);
}

extern "C" void kernel_launch(void* const* d_in, const int* in_sizes, int n_in,
                              void* d_out, int out_size)
{
    (void)in_sizes; (void)n_in; (void)out_size;
    const float* x = (const float*)d_in[0];
    const float* w = (const float*)d_in[1];
    // d_in[2] = edge_index (int64), d_in[3] = batch (int64): dead w.r.t. output.
    float* out = (float*)d_out;
    topkpool_fused_kernel<<<BB, THREADS>>>(x, w, out);
}

// round 3
// speedup vs baseline: 1.4868x; 1.4868x over previous
#include <cuda_runtime.h>
#include <cuda_bf16.h>

// TopKPool_16372415332892
// out[b] = mean_{k in topK} x[row]*tanh((x[row].w)/||w||),  B=256,N=512,D=256,K=256.
// edge_index / batch are dead inputs.

#define BB 256
#define NN 512
#define DD 256
#define KK 256

// Scratch: raw per-node dot products (selection is monotone in this).
__device__ float g_score[BB * NN];

// ---------------- Kernel 1: scores (warp per row) ----------------
// grid = B*N/8 = 16384 blocks, 256 threads (8 warps -> 8 rows/block).
__global__ __launch_bounds__(256)
void score_kernel(const float* __restrict__ x, const float* __restrict__ w)
{
    const int lane = threadIdx.x & 31;
    const int warp = threadIdx.x >> 5;
    const int row  = blockIdx.x * 8 + warp;

    const float4 wa = *reinterpret_cast<const float4*>(w + lane * 4);
    const float4 wb = *reinterpret_cast<const float4*>(w + 128 + lane * 4);

    const float* r = x + (size_t)row * DD;
    const float4 xa = *reinterpret_cast<const float4*>(r + lane * 4);
    const float4 xc = *reinterpret_cast<const float4*>(r + 128 + lane * 4);

    float d = xa.x * wa.x + xa.y * wa.y + xa.z * wa.z + xa.w * wa.w
            + xc.x * wb.x + xc.y * wb.y + xc.z * wb.z + xc.w * wb.w;
    #pragma unroll
    for (int o = 16; o; o >>= 1) d += __shfl_xor_sync(0xffffffffu, d, o);
    if (lane == 0) g_score[row] = d;
}

// ---------------- Kernel 2: rank + gather (block per graph) ----------------
// 1024 threads: col = tid&255, chunk = tid>>8 handles 64 of the K rows.
__global__ __launch_bounds__(1024, 2)
void rank_gather_kernel(const float* __restrict__ x,
                        const float* __restrict__ w,
                        float* __restrict__ out)
{
    __shared__ float sh_score[NN];
    __shared__ float sh_gate[KK];
    __shared__ int   sh_idx[KK];
    __shared__ float sh_part[4 * DD];
    __shared__ float sh_red[8];
    __shared__ float sh_inv;

    const int tid = threadIdx.x;
    const int b   = blockIdx.x;

    // ||w||^-1 (first 256 threads)
    if (tid < 256) {
        float v = w[tid];
        float ssq = v * v;
        #pragma unroll
        for (int o = 16; o; o >>= 1) ssq += __shfl_xor_sync(0xffffffffu, ssq, o);
        if ((tid & 31) == 0) sh_red[tid >> 5] = ssq;
    }
    __syncthreads();
    if (tid == 0) {
        float t = 0.f;
        #pragma unroll
        for (int i = 0; i < 8; i++) t += sh_red[i];
        sh_inv = rsqrtf(t);
    }
    // stage scores into smem (independent of sh_inv; same sync covers both)
    if (tid < NN) sh_score[tid] = g_score[b * NN + tid];
    __syncthreads();

    // Exact rank = count-of-greater, ties -> lower index (matches jax top_k).
    // Rank is unique -> free compaction into dense [0,K) slots.
    if (tid < NN) {
        const float si = sh_score[tid];
        int cnt = 0;
        #pragma unroll 8
        for (int j = 0; j < NN; j++) {
            const float sj = sh_score[j];
            cnt += (sj > si) || (sj == si && j < tid);
        }
        if (cnt < KK) {
            sh_idx[cnt]  = tid;
            sh_gate[cnt] = tanhf(si * sh_inv);
        }
    }
    __syncthreads();

    // Gather: chunk c accumulates rows [c*64, c*64+64), thread owns column col.
    const int col   = tid & (DD - 1);
    const int chunk = tid >> 8;
    const float* xb = x + (size_t)b * NN * DD;

    float acc = 0.f;
    const int k0 = chunk * 64;
    #pragma unroll 8
    for (int k = k0; k < k0 + 64; k++) {
        acc += xb[(size_t)sh_idx[k] * DD + col] * sh_gate[k];
    }
    sh_part[chunk * DD + col] = acc;
    __syncthreads();

    if (tid < DD) {
        float s = sh_part[tid] + sh_part[DD + tid]
                + sh_part[2 * DD + tid] + sh_part[3 * DD + tid];
        out[b * DD + tid] = s * (1.0f / (float)KK);
    }
}

extern "C" void kernel_launch(void* const* d_in, const int* in_sizes, int n_in,
                              void* d_out, int out_size)
{
    (void)in_sizes; (void)n_in; (void)out_size;
    const float* x = (const float*)d_in[0];
    const float* w = (const float*)d_in[1];
    // d_in[2] = edge_index, d_in[3] = batch : dead w.r.t. output.
    float* out = (float*)d_out;

    score_kernel<<<(BB * NN) / 8, 256>>>(x, w);
    rank_gather_kernel<<<BB, 1024>>>(x, w, out);
}